// round 3
// baseline (speedup 1.0000x reference)
#include <cuda_runtime.h>
#include <cstdint>

// Problem constants (fixed by the dataset)
#define N_NODES 100000
#define N_EDGES 200000
#define DIM     256
#define NB      2
#define NC      8
#define TCOLS   (NB * DIM)   // 512

// Scratch: per-node transformed features t[n, b, j] = sum_i h_src[n,i] * P[b,i,j]
// 100000 * 512 floats = 204.8 MB, static device global (allocation-guard safe).
__device__ float g_t[(size_t)N_NODES * TCOLS];

// ---------------------------------------------------------------------------
// Kernel 1: C[M=100000, N=512] = A[100000,256] @ B[256,512]
// where B[k, n] = P[b, k, jl] with b = n>>8, jl = n&255.
// Register-blocked SIMT fp32 GEMM: block tile 128x64, BK=16, 256 threads,
// each thread computes an 8x4 micro-tile.
// ---------------------------------------------------------------------------
__global__ __launch_bounds__(256) void gemm_node_transform(
    const float* __restrict__ A,   // h_src [N_NODES, 256]
    const float* __restrict__ P)   // [NB, 256, 256]
{
    constexpr int BM = 128, BN = 64, BK = 16;
    __shared__ float As[BK][BM];   // transposed A tile: As[k][m]
    __shared__ float Bs[BK][BN];

    const int m0 = blockIdx.x * BM;
    const int n0 = blockIdx.y * BN;          // 64-aligned => tile within one basis
    const int basis = n0 >> 8;
    const int jl0 = n0 & 255;
    const float* Bp = P + (size_t)basis * DIM * DIM + jl0;  // Bp[k*256 + j]

    const int tid = threadIdx.x;
    const int ty = tid >> 4;     // 0..15  -> row group (8 rows each)
    const int tx = tid & 15;     // 0..15  -> col group (4 cols each)

    float acc[8][4];
#pragma unroll
    for (int i = 0; i < 8; i++)
#pragma unroll
        for (int j = 0; j < 4; j++) acc[i][j] = 0.0f;

    // A-tile load mapping: each thread loads 2 float4 along K
    const int ar = tid >> 1;            // 0..127 row within tile
    const int akq = (tid & 1) * 8;      // 0 or 8 (k offset)
    const int gm = m0 + ar;
    const bool arow_ok = (gm < N_NODES);

    // B-tile load mapping: each thread loads 1 float4
    const int br = tid >> 4;            // 0..15 k row
    const int bc = (tid & 15) * 4;      // col

    for (int k0 = 0; k0 < DIM; k0 += BK) {
        // --- load A tile (transposed into As[k][m]) ---
        float4 a0 = make_float4(0.f, 0.f, 0.f, 0.f);
        float4 a1 = make_float4(0.f, 0.f, 0.f, 0.f);
        if (arow_ok) {
            const float* ap = A + (size_t)gm * DIM + k0 + akq;
            a0 = *reinterpret_cast<const float4*>(ap);
            a1 = *reinterpret_cast<const float4*>(ap + 4);
        }
        As[akq + 0][ar] = a0.x; As[akq + 1][ar] = a0.y;
        As[akq + 2][ar] = a0.z; As[akq + 3][ar] = a0.w;
        As[akq + 4][ar] = a1.x; As[akq + 5][ar] = a1.y;
        As[akq + 6][ar] = a1.z; As[akq + 7][ar] = a1.w;

        // --- load B tile ---
        *reinterpret_cast<float4*>(&Bs[br][bc]) =
            *reinterpret_cast<const float4*>(Bp + (size_t)(k0 + br) * DIM + bc);

        __syncthreads();

#pragma unroll
        for (int kk = 0; kk < BK; kk++) {
            float4 av0 = *reinterpret_cast<const float4*>(&As[kk][ty * 8]);
            float4 av1 = *reinterpret_cast<const float4*>(&As[kk][ty * 8 + 4]);
            float4 bv  = *reinterpret_cast<const float4*>(&Bs[kk][tx * 4]);
            float a[8] = {av0.x, av0.y, av0.z, av0.w, av1.x, av1.y, av1.z, av1.w};
            float b[4] = {bv.x, bv.y, bv.z, bv.w};
#pragma unroll
            for (int i = 0; i < 8; i++)
#pragma unroll
                for (int j = 0; j < 4; j++)
                    acc[i][j] = fmaf(a[i], b[j], acc[i][j]);
        }
        __syncthreads();
    }

    // --- write C tile into g_t ---
#pragma unroll
    for (int i = 0; i < 8; i++) {
        int m = m0 + ty * 8 + i;
        if (m < N_NODES) {
            float4 v = make_float4(acc[i][0], acc[i][1], acc[i][2], acc[i][3]);
            *reinterpret_cast<float4*>(&g_t[(size_t)m * TCOLS + n0 + tx * 4]) = v;
        }
    }
}

// ---------------------------------------------------------------------------
// Kernel 2: per-edge gather + dot + combine.
// One warp per edge. Each lane holds float4 slices of t[u,b,:] and h_dst[v,:],
// computes partial dots for both bases, warp-reduces, lanes 0..7 write logits.
// ---------------------------------------------------------------------------
__device__ __forceinline__ float dot4(float4 a, float4 b) {
    return fmaf(a.x, b.x, fmaf(a.y, b.y, fmaf(a.z, b.z, a.w * b.w)));
}

__global__ __launch_bounds__(256) void edge_bilinear(
    const float* __restrict__ h_dst,
    const int*   __restrict__ u_idx,
    const int*   __restrict__ v_idx,
    const float* __restrict__ W,     // [NC, NB] row-major
    float*       __restrict__ out)   // [N_EDGES, NC]
{
    const int gtid = blockIdx.x * blockDim.x + threadIdx.x;
    const int e = gtid >> 5;
    const int lane = threadIdx.x & 31;
    if (e >= N_EDGES) return;

    const int u = u_idx[e];
    const int v = v_idx[e];

    const float4* tu = reinterpret_cast<const float4*>(g_t + (size_t)u * TCOLS);
    const float4* dv = reinterpret_cast<const float4*>(h_dst + (size_t)v * DIM);

    // 256 floats = 64 float4 per basis; 32 lanes -> 2 float4 each
    float4 d0  = dv[lane];
    float4 d1  = dv[lane + 32];
    float4 t00 = tu[lane];          // basis 0, first half
    float4 t01 = tu[lane + 32];     // basis 0, second half
    float4 t10 = tu[lane + 64];     // basis 1, first half
    float4 t11 = tu[lane + 96];     // basis 1, second half

    float s0 = dot4(t00, d0) + dot4(t01, d1);
    float s1 = dot4(t10, d0) + dot4(t11, d1);

#pragma unroll
    for (int off = 16; off > 0; off >>= 1) {
        s0 += __shfl_xor_sync(0xFFFFFFFFu, s0, off);
        s1 += __shfl_xor_sync(0xFFFFFFFFu, s1, off);
    }

    if (lane < NC) {
        float w0 = __ldg(W + lane * NB + 0);
        float w1 = __ldg(W + lane * NB + 1);
        out[(size_t)e * NC + lane] = fmaf(s0, w0, s1 * w1);
    }
}

// ---------------------------------------------------------------------------
// Launch
// ---------------------------------------------------------------------------
extern "C" void kernel_launch(void* const* d_in, const int* in_sizes, int n_in,
                              void* d_out, int out_size)
{
    const float* h_src = (const float*)d_in[0];
    const float* h_dst = (const float*)d_in[1];
    const int*   u_idx = (const int*)d_in[2];
    const int*   v_idx = (const int*)d_in[3];
    const float* P     = (const float*)d_in[4];
    const float* W     = (const float*)d_in[5];
    float* out = (float*)d_out;

    // Kernel 1: node transform GEMM  [100000,256] @ [256,512] -> g_t
    {
        dim3 grid((N_NODES + 127) / 128, TCOLS / 64);
        gemm_node_transform<<<grid, 256>>>(h_src, P);
    }

    // Kernel 2: edge gather + bilinear dot + combine
    {
        int warps_per_block = 256 / 32;
        int blocks = (N_EDGES + warps_per_block - 1) / warps_per_block;
        edge_bilinear<<<blocks, 256>>>(h_dst, u_idx, v_idx, W, out);
    }
}

// round 6
// speedup vs baseline: 2.0607x; 2.0607x over previous
#include <cuda_runtime.h>
#include <cuda_bf16.h>
#include <cstdint>

// ===========================================================================
// Problem constants
// ===========================================================================
#define N_NODES 100000
#define N_EDGES 200000
#define DIM     256
#define NB      2
#define NC      8
#define TCOLS   (NB * DIM)   // 512

// Scratch (device globals: allocation-guard safe)
__device__ float         g_t [(size_t)N_NODES * TCOLS];   // 204.8 MB
__device__ __nv_bfloat16 g_ah[(size_t)N_NODES * DIM];     // A hi [node][k]
__device__ __nv_bfloat16 g_al[(size_t)N_NODES * DIM];     // A lo
__device__ __nv_bfloat16 g_bh[(size_t)TCOLS * DIM];       // B hi [n][k], n=b*256+j
__device__ __nv_bfloat16 g_bl[(size_t)TCOLS * DIM];       // B lo

// ===========================================================================
// Baseline-PTX helpers (sm_80-class only — no 'a' features!)
// ===========================================================================
__device__ __forceinline__ uint32_t smem_u32(const void* p) {
    uint32_t a;
    asm("{ .reg .u64 t; cvta.to.shared.u64 t, %1; cvt.u32.u64 %0, t; }"
        : "=r"(a) : "l"(p));
    return a;
}

#define SWZ(off) ((uint32_t)(off) ^ ((((uint32_t)(off)) >> 3) & 0x70u))

#define CP_ASYNC16(dst, src) \
    asm volatile("cp.async.cg.shared.global [%0], [%1], 16;" \
        :: "r"(dst), "l"(src) : "memory")
#define CP_COMMIT() asm volatile("cp.async.commit_group;" ::: "memory")
#define CP_WAIT(n)  asm volatile("cp.async.wait_group %0;" :: "n"(n) : "memory")

#define LDSM_X4(r0, r1, r2, r3, addr) \
    asm volatile("ldmatrix.sync.aligned.m8n8.x4.shared.b16 {%0,%1,%2,%3}, [%4];" \
        : "=r"(r0), "=r"(r1), "=r"(r2), "=r"(r3) : "r"(addr))

#define MMA_BF16(c, a, b0, b1) \
    asm volatile("mma.sync.aligned.m16n8k16.row.col.f32.bf16.bf16.f32 " \
        "{%0,%1,%2,%3}, {%4,%5,%6,%7}, {%8,%9}, {%0,%1,%2,%3};" \
        : "+f"((c)[0]), "+f"((c)[1]), "+f"((c)[2]), "+f"((c)[3]) \
        : "r"((a)[0]), "r"((a)[1]), "r"((a)[2]), "r"((a)[3]), "r"(b0), "r"(b1))

// ===========================================================================
// Kernel 0a: split A (h_src fp32) -> g_ah / g_al bf16
// ===========================================================================
__global__ __launch_bounds__(256) void prep_A(const float* __restrict__ A)
{
    int idx = blockIdx.x * blockDim.x + threadIdx.x;     // per float4
    if (idx >= N_NODES * (DIM / 4)) return;
    float4 v = reinterpret_cast<const float4*>(A)[idx];

    __nv_bfloat16 hx = __float2bfloat16(v.x), hy = __float2bfloat16(v.y);
    __nv_bfloat16 hz = __float2bfloat16(v.z), hw = __float2bfloat16(v.w);
    __nv_bfloat16 lx = __float2bfloat16(v.x - __bfloat162float(hx));
    __nv_bfloat16 ly = __float2bfloat16(v.y - __bfloat162float(hy));
    __nv_bfloat16 lz = __float2bfloat16(v.z - __bfloat162float(hz));
    __nv_bfloat16 lw = __float2bfloat16(v.w - __bfloat162float(hw));

    __nv_bfloat162 h01 = __halves2bfloat162(hx, hy);
    __nv_bfloat162 h23 = __halves2bfloat162(hz, hw);
    __nv_bfloat162 l01 = __halves2bfloat162(lx, ly);
    __nv_bfloat162 l23 = __halves2bfloat162(lz, lw);

    reinterpret_cast<uint2*>(g_ah)[idx] = make_uint2(*(uint32_t*)&h01, *(uint32_t*)&h23);
    reinterpret_cast<uint2*>(g_al)[idx] = make_uint2(*(uint32_t*)&l01, *(uint32_t*)&l23);
}

// ===========================================================================
// Kernel 0b: split + transpose P -> g_bh / g_bl   [n][k], n = b*256 + j
// ===========================================================================
__global__ __launch_bounds__(256) void prep_B(const float* __restrict__ P)
{
    int idx = blockIdx.x * blockDim.x + threadIdx.x;
    if (idx >= NB * DIM * DIM) return;
    int b = idx >> 16;
    int k = (idx >> 8) & 255;
    int j = idx & 255;
    float v = P[idx];
    __nv_bfloat16 h = __float2bfloat16(v);
    __nv_bfloat16 l = __float2bfloat16(v - __bfloat162float(h));
    int n = b * DIM + j;
    g_bh[(size_t)n * DIM + k] = h;
    g_bl[(size_t)n * DIM + k] = l;
}

// ===========================================================================
// Kernel 1: split-bf16 mma.sync GEMM
//   C[100000, 512] = A[100000,256] @ B^T  (B stored [n][k])
//   C = Ah*Bh + Al*Bh + Ah*Bl  (single fp32 accumulator)
// Tiles: BM=128, BN=128, BK=64. B fully SMEM-resident (hi+lo = 128KB).
// A hi/lo streamed via cp.async, 3 stages, prefetch distance 2.
// B panel stride in SMEM: 128 rows x 128B = 16384 B per kc chunk.
// ===========================================================================
static constexpr int A_STAGE_BYTES = 32768;            // Ah 16K + Al 16K
static constexpr int B_PANEL_BYTES = 16384;            // 128 rows x 128B
static constexpr int SM_B_H = 3 * A_STAGE_BYTES;       // 98304
static constexpr int SM_B_L = SM_B_H + 65536;          // 163840
static constexpr int SMEM_TOTAL = SM_B_L + 65536;      // 229376 (224 KB)

__device__ __forceinline__ void load_A_stage(uint32_t sbA, int m0, int kc,
                                             int buf, int tid)
{
    const uint32_t bh = sbA + buf * A_STAGE_BYTES;
    const uint32_t bl = bh + 16384;
#pragma unroll
    for (int i = 0; i < 4; i++) {
        int c  = tid + i * 256;           // 0..1023 (16B chunks)
        int r  = c >> 3;                  // row 0..127
        int ck = c & 7;                   // chunk in 128B row
        int gr = m0 + r;
        if (gr >= N_NODES) gr = N_NODES - 1;     // clamp (rows unused on store)
        size_t goff = (size_t)gr * DIM + kc * 64 + ck * 8;
        uint32_t soff = SWZ(r * 128 + ck * 16);
        CP_ASYNC16(bh + soff, g_ah + goff);
        CP_ASYNC16(bl + soff, g_al + goff);
    }
}

__global__ __launch_bounds__(256, 1) void gemm_mma()
{
    extern __shared__ char smem[];
    const uint32_t sb    = smem_u32(smem);
    const uint32_t sbA   = sb;
    const uint32_t sbBH  = sb + SM_B_H;
    const uint32_t sbBL  = sb + SM_B_L;

    const int tid  = threadIdx.x;
    const int lane = tid & 31;
    const int wid  = tid >> 5;
    const int warp_m = wid & 3;       // 4 warps along M (32 rows each)
    const int warp_n = wid >> 2;      // 2 warps along N (64 cols each)
    const int m0 = blockIdx.y * 128;
    const int n0 = blockIdx.x * 128;

    // ---- prologue: B (resident) + A stage 0 -> group0; A stage 1 -> group1
#pragma unroll
    for (int i = 0; i < 16; i++) {
        int c  = tid + i * 256;          // 0..4095
        int n  = c >> 5;                 // n row 0..127
        int ck = c & 31;                 // 16B chunk within 512B row
        int kp = ck >> 3;                // k panel 0..3
        int cb = (ck & 7) * 16;          // col byte within panel row
        size_t goff = (size_t)(n0 + n) * DIM + ck * 8;
        uint32_t soff = (uint32_t)kp * B_PANEL_BYTES + SWZ(n * 128 + cb);
        CP_ASYNC16(sbBH + soff, g_bh + goff);
        CP_ASYNC16(sbBL + soff, g_bl + goff);
    }
    load_A_stage(sbA, m0, 0, 0, tid);
    CP_COMMIT();
    load_A_stage(sbA, m0, 1, 1, tid);
    CP_COMMIT();

    float acc[2][8][4];
#pragma unroll
    for (int t = 0; t < 2; t++)
#pragma unroll
        for (int j = 0; j < 8; j++)
#pragma unroll
            for (int q = 0; q < 4; q++) acc[t][j][q] = 0.0f;

    // ldmatrix lane address components
    const int quad  = lane >> 3;
    const int a_row = warp_m * 32 + (quad & 1) * 8 + (lane & 7);
    const int a_cb  = (quad >> 1) * 16;
    const int b_row = warp_n * 64 + (quad >> 1) * 8 + (lane & 7);
    const int b_cb  = (quad & 1) * 16;

    for (int kc = 0; kc < 4; kc++) {
        if (kc < 3) { CP_WAIT(1); } else { CP_WAIT(0); }
        __syncthreads();
        if (kc + 2 <= 3) {
            load_A_stage(sbA, m0, kc + 2, (kc + 2) % 3, tid);
            CP_COMMIT();
        }

        const uint32_t aH = sbA + (uint32_t)(kc % 3) * A_STAGE_BYTES;
        const uint32_t aL = aH + 16384u;
        const uint32_t bH = sbBH + (uint32_t)kc * B_PANEL_BYTES;
        const uint32_t bL = sbBL + (uint32_t)kc * B_PANEL_BYTES;

#pragma unroll
        for (int ks = 0; ks < 4; ks++) {
            uint32_t ah[2][4], al[2][4], bhf[4][4], blf[4][4];
#pragma unroll
            for (int t = 0; t < 2; t++) {
                uint32_t off = SWZ((a_row + t * 16) * 128 + ks * 32 + a_cb);
                LDSM_X4(ah[t][0], ah[t][1], ah[t][2], ah[t][3], aH + off);
                LDSM_X4(al[t][0], al[t][1], al[t][2], al[t][3], aL + off);
            }
#pragma unroll
            for (int j = 0; j < 4; j++) {
                uint32_t off = SWZ((b_row + j * 16) * 128 + ks * 32 + b_cb);
                LDSM_X4(bhf[j][0], bhf[j][1], bhf[j][2], bhf[j][3], bH + off);
                LDSM_X4(blf[j][0], blf[j][1], blf[j][2], blf[j][3], bL + off);
            }
#pragma unroll
            for (int t = 0; t < 2; t++)
#pragma unroll
                for (int j = 0; j < 4; j++) {
                    MMA_BF16(acc[t][2 * j],     ah[t], bhf[j][0], bhf[j][1]);
                    MMA_BF16(acc[t][2 * j + 1], ah[t], bhf[j][2], bhf[j][3]);
                    MMA_BF16(acc[t][2 * j],     al[t], bhf[j][0], bhf[j][1]);
                    MMA_BF16(acc[t][2 * j + 1], al[t], bhf[j][2], bhf[j][3]);
                    MMA_BF16(acc[t][2 * j],     ah[t], blf[j][0], blf[j][1]);
                    MMA_BF16(acc[t][2 * j + 1], ah[t], blf[j][2], blf[j][3]);
                }
        }
    }

    // ---- epilogue: write C tile (fp32) to g_t
    const int mb = m0 + warp_m * 32;
    const int nb = n0 + warp_n * 64;
    const int r0 = lane >> 2;
    const int c0 = (lane & 3) * 2;
#pragma unroll
    for (int t = 0; t < 2; t++) {
#pragma unroll
        for (int nt = 0; nt < 8; nt++) {
            int col = nb + nt * 8 + c0;
            int row = mb + t * 16 + r0;
            if (row < N_NODES)
                *reinterpret_cast<float2*>(&g_t[(size_t)row * TCOLS + col]) =
                    make_float2(acc[t][nt][0], acc[t][nt][1]);
            if (row + 8 < N_NODES)
                *reinterpret_cast<float2*>(&g_t[(size_t)(row + 8) * TCOLS + col]) =
                    make_float2(acc[t][nt][2], acc[t][nt][3]);
        }
    }
}

// ===========================================================================
// Kernel 2: per-edge gather + dot + combine (at HBM roofline already)
// ===========================================================================
__device__ __forceinline__ float dot4(float4 a, float4 b) {
    return fmaf(a.x, b.x, fmaf(a.y, b.y, fmaf(a.z, b.z, a.w * b.w)));
}

__global__ __launch_bounds__(256) void edge_bilinear(
    const float* __restrict__ h_dst,
    const int*   __restrict__ u_idx,
    const int*   __restrict__ v_idx,
    const float* __restrict__ W,
    float*       __restrict__ out)
{
    const int gtid = blockIdx.x * blockDim.x + threadIdx.x;
    const int e = gtid >> 5;
    const int lane = threadIdx.x & 31;
    if (e >= N_EDGES) return;

    const int u = u_idx[e];
    const int v = v_idx[e];

    const float4* tu = reinterpret_cast<const float4*>(g_t + (size_t)u * TCOLS);
    const float4* dv = reinterpret_cast<const float4*>(h_dst + (size_t)v * DIM);

    float4 d0  = dv[lane];
    float4 d1  = dv[lane + 32];
    float4 t00 = tu[lane];
    float4 t01 = tu[lane + 32];
    float4 t10 = tu[lane + 64];
    float4 t11 = tu[lane + 96];

    float s0 = dot4(t00, d0) + dot4(t01, d1);
    float s1 = dot4(t10, d0) + dot4(t11, d1);

#pragma unroll
    for (int off = 16; off > 0; off >>= 1) {
        s0 += __shfl_xor_sync(0xFFFFFFFFu, s0, off);
        s1 += __shfl_xor_sync(0xFFFFFFFFu, s1, off);
    }

    if (lane < NC) {
        float w0 = __ldg(W + lane * NB + 0);
        float w1 = __ldg(W + lane * NB + 1);
        out[(size_t)e * NC + lane] = fmaf(s0, w0, s1 * w1);
    }
}

// ===========================================================================
// Launch
// ===========================================================================
extern "C" void kernel_launch(void* const* d_in, const int* in_sizes, int n_in,
                              void* d_out, int out_size)
{
    const float* h_src = (const float*)d_in[0];
    const float* h_dst = (const float*)d_in[1];
    const int*   u_idx = (const int*)d_in[2];
    const int*   v_idx = (const int*)d_in[3];
    const float* P     = (const float*)d_in[4];
    const float* W     = (const float*)d_in[5];
    float* out = (float*)d_out;

    cudaFuncSetAttribute(gemm_mma,
                         cudaFuncAttributeMaxDynamicSharedMemorySize,
                         SMEM_TOTAL);

    // 0) split inputs into bf16 hi/lo
    prep_A<<<(N_NODES * (DIM / 4) + 255) / 256, 256>>>(h_src);
    prep_B<<<(NB * DIM * DIM + 255) / 256, 256>>>(P);

    // 1) tensor-core node transform -> g_t  (grid: n fastest for L2 A-reuse)
    {
        dim3 grid(TCOLS / 128, (N_NODES + 127) / 128);
        gemm_mma<<<grid, 256, SMEM_TOTAL>>>();
    }

    // 2) edge gather + bilinear dot + combine
    {
        int blocks = (N_EDGES + 7) / 8;
        edge_bilinear<<<blocks, 256>>>(h_dst, u_idx, v_idx, W, out);
    }
}

// round 7
// speedup vs baseline: 2.4190x; 1.1739x over previous
#include <cuda_runtime.h>
#include <cuda_fp16.h>
#include <cstdint>

// ===========================================================================
// Problem constants
// ===========================================================================
#define N_NODES 100000
#define N_EDGES 200000
#define DIM     256
#define NB      2
#define NC      8
#define TCOLS   (NB * DIM)   // 512

// Scratch (device globals: allocation-guard safe)
__device__ float  g_t [(size_t)N_NODES * TCOLS];   // 204.8 MB
__device__ __half g_af[(size_t)N_NODES * DIM];     // A fp16 [node][k]
__device__ __half g_bh[(size_t)TCOLS * DIM];       // B hi [n][k], n=b*256+j
__device__ __half g_bl[(size_t)TCOLS * DIM];       // B lo, scaled x2048

// ===========================================================================
// Baseline-PTX helpers (sm_80-class only — no 'a' features!)
// ===========================================================================
__device__ __forceinline__ uint32_t smem_u32(const void* p) {
    uint32_t a;
    asm("{ .reg .u64 t; cvta.to.shared.u64 t, %1; cvt.u32.u64 %0, t; }"
        : "=r"(a) : "l"(p));
    return a;
}

#define SWZ(off) ((uint32_t)(off) ^ ((((uint32_t)(off)) >> 3) & 0x70u))

#define CP_ASYNC16(dst, src) \
    asm volatile("cp.async.cg.shared.global [%0], [%1], 16;" \
        :: "r"(dst), "l"(src) : "memory")
#define CP_COMMIT() asm volatile("cp.async.commit_group;" ::: "memory")
#define CP_WAIT(n)  asm volatile("cp.async.wait_group %0;" :: "n"(n) : "memory")

#define LDSM_X4(r0, r1, r2, r3, addr) \
    asm volatile("ldmatrix.sync.aligned.m8n8.x4.shared.b16 {%0,%1,%2,%3}, [%4];" \
        : "=r"(r0), "=r"(r1), "=r"(r2), "=r"(r3) : "r"(addr))

#define MMA_F16(c, a, b0, b1) \
    asm volatile("mma.sync.aligned.m16n8k16.row.col.f32.f16.f16.f32 " \
        "{%0,%1,%2,%3}, {%4,%5,%6,%7}, {%8,%9}, {%0,%1,%2,%3};" \
        : "+f"((c)[0]), "+f"((c)[1]), "+f"((c)[2]), "+f"((c)[3]) \
        : "r"((a)[0]), "r"((a)[1]), "r"((a)[2]), "r"((a)[3]), "r"(b0), "r"(b1))

// ===========================================================================
// Kernel 0a: A (h_src fp32) -> g_af fp16
// ===========================================================================
__global__ __launch_bounds__(256) void prep_A(const float* __restrict__ A)
{
    int idx = blockIdx.x * blockDim.x + threadIdx.x;     // per float4
    if (idx >= N_NODES * (DIM / 4)) return;
    float4 v = reinterpret_cast<const float4*>(A)[idx];
    __half2 p01 = __floats2half2_rn(v.x, v.y);
    __half2 p23 = __floats2half2_rn(v.z, v.w);
    reinterpret_cast<uint2*>(g_af)[idx] =
        make_uint2(*(uint32_t*)&p01, *(uint32_t*)&p23);
}

// ===========================================================================
// Kernel 0b: split + transpose P -> g_bh / g_bl (lo scaled x2048), [n][k]
// ===========================================================================
__global__ __launch_bounds__(256) void prep_B(const float* __restrict__ P)
{
    int idx = blockIdx.x * blockDim.x + threadIdx.x;
    if (idx >= NB * DIM * DIM) return;
    int b = idx >> 16;
    int k = (idx >> 8) & 255;
    int j = idx & 255;
    float v = P[idx];
    __half h = __float2half_rn(v);
    float r = v - __half2float(h);
    __half l = __float2half_rn(r * 2048.0f);
    int n = b * DIM + j;
    g_bh[(size_t)n * DIM + k] = h;
    g_bl[(size_t)n * DIM + k] = l;
}

// ===========================================================================
// Kernel 1: 2-pass fp16 mma.sync GEMM
//   C[100000, 512] = A[100000,256] @ B^T   (B stored [n][k])
//   C = A*Bh + (A*Bl_scaled) / 2048   (two fp32 accumulators)
// Tiles: BM=128, BN=128, BK=64. B hi/lo fully SMEM-resident (128KB).
// A fp16 streamed via cp.async, 3 stages (16KB each), prefetch distance 2.
// ===========================================================================
static constexpr int A_STAGE_BYTES = 16384;            // 128 rows x 128B
static constexpr int B_PANEL_BYTES = 16384;            // 128 rows x 128B
static constexpr int SM_B_H = 3 * A_STAGE_BYTES;       // 49152
static constexpr int SM_B_L = SM_B_H + 65536;          // 114688
static constexpr int SMEM_TOTAL = SM_B_L + 65536;      // 180224 (176 KB)

__device__ __forceinline__ void load_A_stage(uint32_t sbA, int m0, int kc,
                                             int buf, int tid)
{
    const uint32_t base = sbA + buf * A_STAGE_BYTES;
#pragma unroll
    for (int i = 0; i < 4; i++) {
        int c  = tid + i * 256;           // 0..1023 (16B chunks)
        int r  = c >> 3;                  // row 0..127
        int ck = c & 7;                   // chunk in 128B row
        int gr = m0 + r;
        if (gr >= N_NODES) gr = N_NODES - 1;     // clamp (rows unused on store)
        size_t goff = (size_t)gr * DIM + kc * 64 + ck * 8;
        uint32_t soff = SWZ(r * 128 + ck * 16);
        CP_ASYNC16(base + soff, g_af + goff);
    }
}

__global__ __launch_bounds__(256, 1) void gemm_mma()
{
    extern __shared__ char smem[];
    const uint32_t sb    = smem_u32(smem);
    const uint32_t sbA   = sb;
    const uint32_t sbBH  = sb + SM_B_H;
    const uint32_t sbBL  = sb + SM_B_L;

    const int tid  = threadIdx.x;
    const int lane = tid & 31;
    const int wid  = tid >> 5;
    const int warp_m = wid & 3;       // 4 warps along M (32 rows each)
    const int warp_n = wid >> 2;      // 2 warps along N (64 cols each)
    const int m0 = blockIdx.y * 128;
    const int n0 = blockIdx.x * 128;

    // ---- prologue: B (resident) + A stage 0 -> group0; A stage 1 -> group1
#pragma unroll
    for (int i = 0; i < 16; i++) {
        int c  = tid + i * 256;          // 0..4095
        int n  = c >> 5;                 // n row 0..127
        int ck = c & 31;                 // 16B chunk within 512B row
        int kp = ck >> 3;                // k panel 0..3
        int cb = (ck & 7) * 16;          // col byte within panel row
        size_t goff = (size_t)(n0 + n) * DIM + ck * 8;
        uint32_t soff = (uint32_t)kp * B_PANEL_BYTES + SWZ(n * 128 + cb);
        CP_ASYNC16(sbBH + soff, g_bh + goff);
        CP_ASYNC16(sbBL + soff, g_bl + goff);
    }
    load_A_stage(sbA, m0, 0, 0, tid);
    CP_COMMIT();
    load_A_stage(sbA, m0, 1, 1, tid);
    CP_COMMIT();

    float acc[2][8][4];    // A*Bh
    float acc2[2][8][4];   // A*Bl_scaled
#pragma unroll
    for (int t = 0; t < 2; t++)
#pragma unroll
        for (int j = 0; j < 8; j++)
#pragma unroll
            for (int q = 0; q < 4; q++) { acc[t][j][q] = 0.0f; acc2[t][j][q] = 0.0f; }

    // ldmatrix lane address components
    const int quad  = lane >> 3;
    const int a_row = warp_m * 32 + (quad & 1) * 8 + (lane & 7);
    const int a_cb  = (quad >> 1) * 16;
    const int b_row = warp_n * 64 + (quad >> 1) * 8 + (lane & 7);
    const int b_cb  = (quad & 1) * 16;

    for (int kc = 0; kc < 4; kc++) {
        if (kc < 3) { CP_WAIT(1); } else { CP_WAIT(0); }
        __syncthreads();
        if (kc + 2 <= 3) {
            load_A_stage(sbA, m0, kc + 2, (kc + 2) % 3, tid);
            CP_COMMIT();
        }

        const uint32_t aS = sbA + (uint32_t)(kc % 3) * A_STAGE_BYTES;
        const uint32_t bH = sbBH + (uint32_t)kc * B_PANEL_BYTES;
        const uint32_t bL = sbBL + (uint32_t)kc * B_PANEL_BYTES;

#pragma unroll
        for (int ks = 0; ks < 4; ks++) {
            uint32_t af[2][4], bhf[4][4], blf[4][4];
#pragma unroll
            for (int t = 0; t < 2; t++) {
                uint32_t off = SWZ((a_row + t * 16) * 128 + ks * 32 + a_cb);
                LDSM_X4(af[t][0], af[t][1], af[t][2], af[t][3], aS + off);
            }
#pragma unroll
            for (int j = 0; j < 4; j++) {
                uint32_t off = SWZ((b_row + j * 16) * 128 + ks * 32 + b_cb);
                LDSM_X4(bhf[j][0], bhf[j][1], bhf[j][2], bhf[j][3], bH + off);
                LDSM_X4(blf[j][0], blf[j][1], blf[j][2], blf[j][3], bL + off);
            }
#pragma unroll
            for (int t = 0; t < 2; t++)
#pragma unroll
                for (int j = 0; j < 4; j++) {
                    MMA_F16(acc [t][2 * j],     af[t], bhf[j][0], bhf[j][1]);
                    MMA_F16(acc [t][2 * j + 1], af[t], bhf[j][2], bhf[j][3]);
                    MMA_F16(acc2[t][2 * j],     af[t], blf[j][0], blf[j][1]);
                    MMA_F16(acc2[t][2 * j + 1], af[t], blf[j][2], blf[j][3]);
                }
        }
    }

    // ---- epilogue: C = acc + acc2/2048, write fp32 to g_t
    constexpr float INV_SCALE = 1.0f / 2048.0f;
    const int mb = m0 + warp_m * 32;
    const int nb = n0 + warp_n * 64;
    const int r0 = lane >> 2;
    const int c0 = (lane & 3) * 2;
#pragma unroll
    for (int t = 0; t < 2; t++) {
#pragma unroll
        for (int nt = 0; nt < 8; nt++) {
            int col = nb + nt * 8 + c0;
            int row = mb + t * 16 + r0;
            float v0 = fmaf(acc2[t][nt][0], INV_SCALE, acc[t][nt][0]);
            float v1 = fmaf(acc2[t][nt][1], INV_SCALE, acc[t][nt][1]);
            float v2 = fmaf(acc2[t][nt][2], INV_SCALE, acc[t][nt][2]);
            float v3 = fmaf(acc2[t][nt][3], INV_SCALE, acc[t][nt][3]);
            if (row < N_NODES)
                *reinterpret_cast<float2*>(&g_t[(size_t)row * TCOLS + col]) =
                    make_float2(v0, v1);
            if (row + 8 < N_NODES)
                *reinterpret_cast<float2*>(&g_t[(size_t)(row + 8) * TCOLS + col]) =
                    make_float2(v2, v3);
        }
    }
}

// ===========================================================================
// Kernel 2: per-edge gather + dot + combine (at HBM roofline already)
// ===========================================================================
__device__ __forceinline__ float dot4(float4 a, float4 b) {
    return fmaf(a.x, b.x, fmaf(a.y, b.y, fmaf(a.z, b.z, a.w * b.w)));
}

__global__ __launch_bounds__(256) void edge_bilinear(
    const float* __restrict__ h_dst,
    const int*   __restrict__ u_idx,
    const int*   __restrict__ v_idx,
    const float* __restrict__ W,
    float*       __restrict__ out)
{
    const int gtid = blockIdx.x * blockDim.x + threadIdx.x;
    const int e = gtid >> 5;
    const int lane = threadIdx.x & 31;
    if (e >= N_EDGES) return;

    const int u = u_idx[e];
    const int v = v_idx[e];

    const float4* tu = reinterpret_cast<const float4*>(g_t + (size_t)u * TCOLS);
    const float4* dv = reinterpret_cast<const float4*>(h_dst + (size_t)v * DIM);

    float4 d0  = dv[lane];
    float4 d1  = dv[lane + 32];
    float4 t00 = tu[lane];
    float4 t01 = tu[lane + 32];
    float4 t10 = tu[lane + 64];
    float4 t11 = tu[lane + 96];

    float s0 = dot4(t00, d0) + dot4(t01, d1);
    float s1 = dot4(t10, d0) + dot4(t11, d1);

#pragma unroll
    for (int off = 16; off > 0; off >>= 1) {
        s0 += __shfl_xor_sync(0xFFFFFFFFu, s0, off);
        s1 += __shfl_xor_sync(0xFFFFFFFFu, s1, off);
    }

    if (lane < NC) {
        float w0 = __ldg(W + lane * NB + 0);
        float w1 = __ldg(W + lane * NB + 1);
        out[(size_t)e * NC + lane] = fmaf(s0, w0, s1 * w1);
    }
}

// ===========================================================================
// Launch
// ===========================================================================
extern "C" void kernel_launch(void* const* d_in, const int* in_sizes, int n_in,
                              void* d_out, int out_size)
{
    const float* h_src = (const float*)d_in[0];
    const float* h_dst = (const float*)d_in[1];
    const int*   u_idx = (const int*)d_in[2];
    const int*   v_idx = (const int*)d_in[3];
    const float* P     = (const float*)d_in[4];
    const float* W     = (const float*)d_in[5];
    float* out = (float*)d_out;

    cudaFuncSetAttribute(gemm_mma,
                         cudaFuncAttributeMaxDynamicSharedMemorySize,
                         SMEM_TOTAL);

    // 0) convert inputs
    prep_A<<<(N_NODES * (DIM / 4) + 255) / 256, 256>>>(h_src);
    prep_B<<<(NB * DIM * DIM + 255) / 256, 256>>>(P);

    // 1) tensor-core node transform -> g_t  (grid: n fastest for L2 A-reuse)
    {
        dim3 grid(TCOLS / 128, (N_NODES + 127) / 128);
        gemm_mma<<<grid, 256, SMEM_TOTAL>>>();
    }

    // 2) edge gather + bilinear dot + combine
    {
        int blocks = (N_EDGES + 7) / 8;
        edge_bilinear<<<blocks, 256>>>(h_dst, u_idx, v_idx, W, out);
    }
}

// round 8
// speedup vs baseline: 4.1964x; 1.7347x over previous
#include <cuda_runtime.h>
#include <cuda_fp16.h>
#include <cstdint>

// ===========================================================================
// Problem constants
// ===========================================================================
#define N_NODES 100000
#define N_EDGES 200000
#define DIM     256
#define NB      2
#define NC      8
#define TCOLS   (NB * DIM)   // 512

// Scratch (device globals: allocation-guard safe)
__device__ __half g_tf[(size_t)N_NODES * TCOLS];   // t fp16, 102.4 MB
__device__ __half g_af[(size_t)N_NODES * DIM];     // A fp16 [node][k]
__device__ __half g_bf[(size_t)TCOLS * DIM];       // B fp16 [n][k], n=b*256+j

// ===========================================================================
// Baseline-PTX helpers (sm_80-class only — no 'a' features!)
// ===========================================================================
__device__ __forceinline__ uint32_t smem_u32(const void* p) {
    uint32_t a;
    asm("{ .reg .u64 t; cvta.to.shared.u64 t, %1; cvt.u32.u64 %0, t; }"
        : "=r"(a) : "l"(p));
    return a;
}

#define SWZ(off) ((uint32_t)(off) ^ ((((uint32_t)(off)) >> 3) & 0x70u))

#define CP_ASYNC16(dst, src) \
    asm volatile("cp.async.cg.shared.global [%0], [%1], 16;" \
        :: "r"(dst), "l"(src) : "memory")
#define CP_COMMIT() asm volatile("cp.async.commit_group;" ::: "memory")
#define CP_WAIT(n)  asm volatile("cp.async.wait_group %0;" :: "n"(n) : "memory")

#define LDSM_X4(r0, r1, r2, r3, addr) \
    asm volatile("ldmatrix.sync.aligned.m8n8.x4.shared.b16 {%0,%1,%2,%3}, [%4];" \
        : "=r"(r0), "=r"(r1), "=r"(r2), "=r"(r3) : "r"(addr))

#define MMA_F16(c, a, b0, b1) \
    asm volatile("mma.sync.aligned.m16n8k16.row.col.f32.f16.f16.f32 " \
        "{%0,%1,%2,%3}, {%4,%5,%6,%7}, {%8,%9}, {%0,%1,%2,%3};" \
        : "+f"((c)[0]), "+f"((c)[1]), "+f"((c)[2]), "+f"((c)[3]) \
        : "r"((a)[0]), "r"((a)[1]), "r"((a)[2]), "r"((a)[3]), "r"(b0), "r"(b1))

// ===========================================================================
// Kernel 0a: A (h_src fp32) -> g_af fp16
// ===========================================================================
__global__ __launch_bounds__(256) void prep_A(const float* __restrict__ A)
{
    int idx = blockIdx.x * blockDim.x + threadIdx.x;     // per float4
    if (idx >= N_NODES * (DIM / 4)) return;
    float4 v = reinterpret_cast<const float4*>(A)[idx];
    __half2 p01 = __floats2half2_rn(v.x, v.y);
    __half2 p23 = __floats2half2_rn(v.z, v.w);
    reinterpret_cast<uint2*>(g_af)[idx] =
        make_uint2(*(uint32_t*)&p01, *(uint32_t*)&p23);
}

// ===========================================================================
// Kernel 0b: transpose P -> g_bf fp16, [n][k], n = b*256 + j
// ===========================================================================
__global__ __launch_bounds__(256) void prep_B(const float* __restrict__ P)
{
    int idx = blockIdx.x * blockDim.x + threadIdx.x;
    if (idx >= NB * DIM * DIM) return;
    int b = idx >> 16;
    int k = (idx >> 8) & 255;
    int j = idx & 255;
    int n = b * DIM + j;
    g_bf[(size_t)n * DIM + k] = __float2half_rn(P[idx]);
}

// ===========================================================================
// Kernel 1: single-pass fp16 mma.sync GEMM
//   t[100000, 512] = A[100000,256] @ B^T   (B stored [n][k]), output fp16
// Tiles: BM=128, BN=128, BK=64. B fully SMEM-resident (64KB).
// A fp16 streamed via cp.async, 3 stages (16KB each), prefetch distance 2.
// SMEM total 112KB -> 2 CTAs/SM.
// ===========================================================================
static constexpr int A_STAGE_BYTES = 16384;            // 128 rows x 128B
static constexpr int B_PANEL_BYTES = 16384;            // 128 rows x 128B
static constexpr int SM_B  = 3 * A_STAGE_BYTES;        // 49152
static constexpr int SMEM_TOTAL = SM_B + 65536;        // 114688 (112 KB)

__device__ __forceinline__ void load_A_stage(uint32_t sbA, int m0, int kc,
                                             int buf, int tid)
{
    const uint32_t base = sbA + buf * A_STAGE_BYTES;
#pragma unroll
    for (int i = 0; i < 4; i++) {
        int c  = tid + i * 256;           // 0..1023 (16B chunks)
        int r  = c >> 3;                  // row 0..127
        int ck = c & 7;                   // chunk in 128B row
        int gr = m0 + r;
        if (gr >= N_NODES) gr = N_NODES - 1;     // clamp (rows unused on store)
        size_t goff = (size_t)gr * DIM + kc * 64 + ck * 8;
        uint32_t soff = SWZ(r * 128 + ck * 16);
        CP_ASYNC16(base + soff, g_af + goff);
    }
}

__global__ __launch_bounds__(256, 2) void gemm_mma()
{
    extern __shared__ char smem[];
    const uint32_t sb   = smem_u32(smem);
    const uint32_t sbA  = sb;
    const uint32_t sbB  = sb + SM_B;

    const int tid  = threadIdx.x;
    const int lane = tid & 31;
    const int wid  = tid >> 5;
    const int warp_m = wid & 3;       // 4 warps along M (32 rows each)
    const int warp_n = wid >> 2;      // 2 warps along N (64 cols each)
    const int m0 = blockIdx.y * 128;
    const int n0 = blockIdx.x * 128;

    // ---- prologue: B (resident) + A stage 0 -> group0; A stage 1 -> group1
#pragma unroll
    for (int i = 0; i < 16; i++) {
        int c  = tid + i * 256;          // 0..4095
        int n  = c >> 5;                 // n row 0..127
        int ck = c & 31;                 // 16B chunk within 512B row
        int kp = ck >> 3;                // k panel 0..3
        int cb = (ck & 7) * 16;          // col byte within panel row
        size_t goff = (size_t)(n0 + n) * DIM + ck * 8;
        uint32_t soff = (uint32_t)kp * B_PANEL_BYTES + SWZ(n * 128 + cb);
        CP_ASYNC16(sbB + soff, g_bf + goff);
    }
    load_A_stage(sbA, m0, 0, 0, tid);
    CP_COMMIT();
    load_A_stage(sbA, m0, 1, 1, tid);
    CP_COMMIT();

    float acc[2][8][4];
#pragma unroll
    for (int t = 0; t < 2; t++)
#pragma unroll
        for (int j = 0; j < 8; j++)
#pragma unroll
            for (int q = 0; q < 4; q++) acc[t][j][q] = 0.0f;

    // ldmatrix lane address components
    const int quad  = lane >> 3;
    const int a_row = warp_m * 32 + (quad & 1) * 8 + (lane & 7);
    const int a_cb  = (quad >> 1) * 16;
    const int b_row = warp_n * 64 + (quad >> 1) * 8 + (lane & 7);
    const int b_cb  = (quad & 1) * 16;

    for (int kc = 0; kc < 4; kc++) {
        if (kc < 3) { CP_WAIT(1); } else { CP_WAIT(0); }
        __syncthreads();
        if (kc + 2 <= 3) {
            load_A_stage(sbA, m0, kc + 2, (kc + 2) % 3, tid);
            CP_COMMIT();
        }

        const uint32_t aS = sbA + (uint32_t)(kc % 3) * A_STAGE_BYTES;
        const uint32_t bS = sbB + (uint32_t)kc * B_PANEL_BYTES;

#pragma unroll
        for (int ks = 0; ks < 4; ks++) {
            uint32_t af[2][4], bf[4][4];
#pragma unroll
            for (int t = 0; t < 2; t++) {
                uint32_t off = SWZ((a_row + t * 16) * 128 + ks * 32 + a_cb);
                LDSM_X4(af[t][0], af[t][1], af[t][2], af[t][3], aS + off);
            }
#pragma unroll
            for (int j = 0; j < 4; j++) {
                uint32_t off = SWZ((b_row + j * 16) * 128 + ks * 32 + b_cb);
                LDSM_X4(bf[j][0], bf[j][1], bf[j][2], bf[j][3], bS + off);
            }
#pragma unroll
            for (int t = 0; t < 2; t++)
#pragma unroll
                for (int j = 0; j < 4; j++) {
                    MMA_F16(acc[t][2 * j],     af[t], bf[j][0], bf[j][1]);
                    MMA_F16(acc[t][2 * j + 1], af[t], bf[j][2], bf[j][3]);
                }
        }
    }

    // ---- epilogue: write t tile as fp16 to g_tf
    const int mb = m0 + warp_m * 32;
    const int nb = n0 + warp_n * 64;
    const int r0 = lane >> 2;
    const int c0 = (lane & 3) * 2;
#pragma unroll
    for (int t = 0; t < 2; t++) {
#pragma unroll
        for (int nt = 0; nt < 8; nt++) {
            int col = nb + nt * 8 + c0;
            int row = mb + t * 16 + r0;
            __half2 p01 = __floats2half2_rn(acc[t][nt][0], acc[t][nt][1]);
            __half2 p23 = __floats2half2_rn(acc[t][nt][2], acc[t][nt][3]);
            if (row < N_NODES)
                *reinterpret_cast<__half2*>(&g_tf[(size_t)row * TCOLS + col]) = p01;
            if (row + 8 < N_NODES)
                *reinterpret_cast<__half2*>(&g_tf[(size_t)(row + 8) * TCOLS + col]) = p23;
        }
    }
}

// ===========================================================================
// Kernel 2: per-edge gather + dot + combine (t now fp16: half the traffic)
// ===========================================================================
__global__ __launch_bounds__(256) void edge_bilinear(
    const float* __restrict__ h_dst,
    const int*   __restrict__ u_idx,
    const int*   __restrict__ v_idx,
    const float* __restrict__ W,
    float*       __restrict__ out)
{
    const int gtid = blockIdx.x * blockDim.x + threadIdx.x;
    const int e = gtid >> 5;
    const int lane = threadIdx.x & 31;
    if (e >= N_EDGES) return;

    const int u = u_idx[e];
    const int v = v_idx[e];

    const uint4*  tu4 = reinterpret_cast<const uint4*>(g_tf + (size_t)u * TCOLS);
    const float4* dv  = reinterpret_cast<const float4*>(h_dst + (size_t)v * DIM);

    // lane handles k = lane*8 .. lane*8+7 for both bases
    uint4  q0 = tu4[lane];        // basis 0: 8 halfs
    uint4  q1 = tu4[lane + 32];   // basis 1: 8 halfs (offset 256 halfs)
    float4 dA = dv[2 * lane];
    float4 dB = dv[2 * lane + 1];

    float s0, s1;
    {
        float2 f;
        f = __half22float2(*reinterpret_cast<__half2*>(&q0.x));
        s0 = fmaf(f.x, dA.x, f.y * dA.y);
        f = __half22float2(*reinterpret_cast<__half2*>(&q0.y));
        s0 = fmaf(f.x, dA.z, fmaf(f.y, dA.w, s0));
        f = __half22float2(*reinterpret_cast<__half2*>(&q0.z));
        s0 = fmaf(f.x, dB.x, fmaf(f.y, dB.y, s0));
        f = __half22float2(*reinterpret_cast<__half2*>(&q0.w));
        s0 = fmaf(f.x, dB.z, fmaf(f.y, dB.w, s0));

        f = __half22float2(*reinterpret_cast<__half2*>(&q1.x));
        s1 = fmaf(f.x, dA.x, f.y * dA.y);
        f = __half22float2(*reinterpret_cast<__half2*>(&q1.y));
        s1 = fmaf(f.x, dA.z, fmaf(f.y, dA.w, s1));
        f = __half22float2(*reinterpret_cast<__half2*>(&q1.z));
        s1 = fmaf(f.x, dB.x, fmaf(f.y, dB.y, s1));
        f = __half22float2(*reinterpret_cast<__half2*>(&q1.w));
        s1 = fmaf(f.x, dB.z, fmaf(f.y, dB.w, s1));
    }

#pragma unroll
    for (int off = 16; off > 0; off >>= 1) {
        s0 += __shfl_xor_sync(0xFFFFFFFFu, s0, off);
        s1 += __shfl_xor_sync(0xFFFFFFFFu, s1, off);
    }

    if (lane < NC) {
        float w0 = __ldg(W + lane * NB + 0);
        float w1 = __ldg(W + lane * NB + 1);
        out[(size_t)e * NC + lane] = fmaf(s0, w0, s1 * w1);
    }
}

// ===========================================================================
// Launch
// ===========================================================================
extern "C" void kernel_launch(void* const* d_in, const int* in_sizes, int n_in,
                              void* d_out, int out_size)
{
    const float* h_src = (const float*)d_in[0];
    const float* h_dst = (const float*)d_in[1];
    const int*   u_idx = (const int*)d_in[2];
    const int*   v_idx = (const int*)d_in[3];
    const float* P     = (const float*)d_in[4];
    const float* W     = (const float*)d_in[5];
    float* out = (float*)d_out;

    cudaFuncSetAttribute(gemm_mma,
                         cudaFuncAttributeMaxDynamicSharedMemorySize,
                         SMEM_TOTAL);

    // 0) convert inputs to fp16
    prep_A<<<(N_NODES * (DIM / 4) + 255) / 256, 256>>>(h_src);
    prep_B<<<(NB * DIM * DIM + 255) / 256, 256>>>(P);

    // 1) tensor-core node transform -> g_tf  (grid: n fastest for L2 A-reuse)
    {
        dim3 grid(TCOLS / 128, (N_NODES + 127) / 128);
        gemm_mma<<<grid, 256, SMEM_TOTAL>>>();
    }

    // 2) edge gather + bilinear dot + combine
    {
        int blocks = (N_EDGES + 7) / 8;
        edge_bilinear<<<blocks, 256>>>(h_dst, u_idx, v_idx, W, out);
    }
}